// round 17
// baseline (speedup 1.0000x reference)
#include <cuda_runtime.h>

#define BB 2
#define NN 16384
#define KK 16
#define CC 64
#define AA 8
#define PTS (BB*NN)          // 32768 points
#define ITEMS (PTS*KK)       // 524288 (b,n,k) items
#define EVEN_GRID 592        // 4 blocks * 148 SMs

typedef unsigned long long u64t;

// ---------------- packed f32x2 helpers (Blackwell FFMA2/FADD2/FMUL2) -------
__device__ __forceinline__ u64t pk2(float lo, float hi) {
    u64t r; asm("mov.b64 %0, {%1, %2};" : "=l"(r) : "f"(lo), "f"(hi)); return r;
}
__device__ __forceinline__ void upk2(u64t v, float& lo, float& hi) {
    asm("mov.b64 {%0, %1}, %2;" : "=f"(lo), "=f"(hi) : "l"(v));
}
__device__ __forceinline__ u64t fma2p(u64t a, u64t b, u64t c) {
    u64t r; asm("fma.rn.f32x2 %0, %1, %2, %3;" : "=l"(r) : "l"(a), "l"(b), "l"(c)); return r;
}
__device__ __forceinline__ u64t add2p(u64t a, u64t b) {
    u64t r; asm("add.rn.f32x2 %0, %1, %2;" : "=l"(r) : "l"(a), "l"(b)); return r;
}
__device__ __forceinline__ u64t mul2p(u64t a, u64t b) {
    u64t r; asm("mul.rn.f32x2 %0, %1, %2;" : "=l"(r) : "l"(a), "l"(b)); return r;
}

// ---------------- scratch (device globals; no allocation allowed) ----------
__device__ float    g_q [PTS*CC];
__device__ float    g_k [PTS*CC];
__device__ float    g_v [PTS*CC];
__device__ float    g_d1[ITEMS*3];
__device__ float    g_h1[ITEMS*AA];
// acc layout: [0..2]=d_sum [3..5]=d_sq [6..69]=g1_sum [70..133]=g1_sq
//             [134..141]=g2_sum [142..149]=g2_sq
__device__ double   g_acc[150];
// bn layout: [0..2]=a_d [3..5]=b_d [6..69]=a1 [70..133]=b1 [134..141]=a2 [142..149]=b2
__device__ float    g_bn[150];
__device__ unsigned g_ctr[4];    // 0=d1, 1=g1s, 2=h1

// last-block detector: returns true in exactly one block, after all others
// have finished their g_acc contributions.
__device__ __forceinline__ bool last_block(int ctrId, int t, int* sFlag) {
    __syncthreads();
    if (t == 0) {
        __threadfence();
        *sFlag = (atomicAdd(&g_ctr[ctrId], 1u) == gridDim.x - 1) ? 1 : 0;
    }
    __syncthreads();
    return *sFlag != 0;
}

// ---------------- kernel 1: q/k/v linear (4x4 register-tiled GEMM) ---------
__global__ void __launch_bounds__(256) k_qkv(
                      const float* __restrict__ feat,
                      const float* __restrict__ Wq, const float* __restrict__ bq,
                      const float* __restrict__ Wk, const float* __restrict__ bk,
                      const float* __restrict__ Wv, const float* __restrict__ bv) {
    if (blockIdx.x == 0) {
        if (threadIdx.x < 150) g_acc[threadIdx.x] = 0.0;
        else if (threadIdx.x < 154) g_ctr[threadIdx.x - 150] = 0u;
    }
    __shared__ float sF[64][65];
    __shared__ float sW[64][64];
    const int t  = threadIdx.x;        // 256
    const int tx = t & 15;             // col group: cols 4tx..4tx+3
    const int ty = t >> 4;             // row base:  rows ty, ty+16, ty+32, ty+48
    const int rowBase = blockIdx.x * 64;
    for (int i = t; i < 4096; i += 256) sF[i>>6][i&63] = feat[rowBase*64 + i];
    __syncthreads();
    for (int m = 0; m < 3; m++) {
        const float* W    = (m==0) ? Wq : ((m==1) ? Wk : Wv);
        const float* bptr = (m==0) ? bq : ((m==1) ? bk : bv);
        float* outp       = (m==0) ? g_q : ((m==1) ? g_k : g_v);
        for (int i = t; i < 4096; i += 256) sW[i>>6][i&63] = W[i];
        __syncthreads();
        const float4 bias = *(const float4*)(bptr + 4*tx);
        float4 acc[4];
        #pragma unroll
        for (int r = 0; r < 4; r++) acc[r] = bias;
        #pragma unroll
        for (int i = 0; i < 64; i++) {
            const float4 wv = *(const float4*)&sW[i][4*tx];
            const float f0 = sF[ty     ][i];
            const float f1 = sF[ty + 16][i];
            const float f2 = sF[ty + 32][i];
            const float f3 = sF[ty + 48][i];
            acc[0].x += f0*wv.x; acc[0].y += f0*wv.y; acc[0].z += f0*wv.z; acc[0].w += f0*wv.w;
            acc[1].x += f1*wv.x; acc[1].y += f1*wv.y; acc[1].z += f1*wv.z; acc[1].w += f1*wv.w;
            acc[2].x += f2*wv.x; acc[2].y += f2*wv.y; acc[2].z += f2*wv.z; acc[2].w += f2*wv.w;
            acc[3].x += f3*wv.x; acc[3].y += f3*wv.y; acc[3].z += f3*wv.z; acc[3].w += f3*wv.w;
        }
        #pragma unroll
        for (int r = 0; r < 4; r++)
            *(float4*)&outp[(rowBase + ty + 16*r)*CC + 4*tx] = acc[r];
        __syncthreads();
    }
}

// ---------------- kernel 2: d1 = rel @ Wd1 + bd1, stats, inline d-BN fin ---
__global__ void __launch_bounds__(256) k_d1(
                     const float* __restrict__ xyz, const int* __restrict__ knn,
                     const float* __restrict__ Wd1, const float* __restrict__ bd1,
                     const float* __restrict__ gd, const float* __restrict__ bed) {
    __shared__ float red[6];
    __shared__ int sLast;
    if (threadIdx.x < 6) red[threadIdx.x] = 0.f;
    __syncthreads();
    float w[9], bb[3];
    #pragma unroll
    for (int i = 0; i < 9; i++) w[i] = Wd1[i];
    #pragma unroll
    for (int i = 0; i < 3; i++) bb[i] = bd1[i];
    float s[3] = {0,0,0}, qq[3] = {0,0,0};
    const int stride = gridDim.x * blockDim.x;
    for (int id = blockIdx.x*blockDim.x + threadIdx.x; id < ITEMS; id += stride) {
        const int p = id >> 4;
        const int b = p >> 14;
        const int n = p & (NN-1);
        const int j = knn[id];
        const float* xc = xyz + (b*NN + n)*3;
        const float* xn = xyz + (b*NN + j)*3;
        const float r0 = xc[0]-xn[0], r1 = xc[1]-xn[1], r2 = xc[2]-xn[2];
        #pragma unroll
        for (int c = 0; c < 3; c++) {
            const float d = r0*w[c] + r1*w[3+c] + r2*w[6+c] + bb[c];
            g_d1[id*3 + c] = d;
            s[c] += d; qq[c] += d*d;
        }
    }
    #pragma unroll
    for (int c = 0; c < 3; c++) {
        #pragma unroll
        for (int off = 16; off; off >>= 1) {
            s[c]  += __shfl_xor_sync(0xFFFFFFFFu, s[c],  off);
            qq[c] += __shfl_xor_sync(0xFFFFFFFFu, qq[c], off);
        }
    }
    if ((threadIdx.x & 31) == 0) {
        #pragma unroll
        for (int c = 0; c < 3; c++) {
            atomicAdd(&red[c],     s[c]);
            atomicAdd(&red[3 + c], qq[c]);
        }
    }
    __syncthreads();
    if (threadIdx.x < 6)
        atomicAdd(&g_acc[threadIdx.x], (double)red[threadIdx.x]);
    // last block finalizes d-BN into g_bn[0..5]
    if (last_block(0, threadIdx.x, &sLast)) {
        const int c = threadIdx.x;
        if (c < 3) {
            const double inv = 1.0 / (double)ITEMS;
            const double m = __ldcg(&g_acc[c])     * inv;
            const double v = __ldcg(&g_acc[3 + c]) * inv - m*m;
            const float a = gd[c] * rsqrtf((float)v + 1e-5f);
            g_bn[c]     = a;
            g_bn[3 + c] = bed[c] - (float)m * a;
        }
    }
}

// ---------------- kernel 3: attn_in stats (packed f32x2) + g1-BN finalize --
__global__ void __launch_bounds__(256, 4) k_g1s(
                      const int* __restrict__ knn, const float* __restrict__ Wd2,
                      const float* __restrict__ bd2p,
                      const float* __restrict__ g1g, const float* __restrict__ be1) {
    __shared__ u64t  st[8][2][16][3];     // duplicated (t,t) pairs
    __shared__ int   sj[8][2][16];
    __shared__ float red[128];   // [0..63]=sum per channel, [64..127]=sq
    __shared__ int   sLast;
    const int t = threadIdx.x;
    if (t < 128) red[t] = 0.f;
    __syncthreads();
    const int lane = t & 31, w = t >> 5;
    const int warp = (blockIdx.x*blockDim.x + t) >> 5;
    const int nw   = (gridDim.x*blockDim.x) >> 5;
    const int c = lane * 2;
    const float ad0=g_bn[0], ad1=g_bn[1], ad2=g_bn[2];
    const float bd0=g_bn[3], bd1v=g_bn[4], bd2v=g_bn[5];
    const float2 wr0 = *(const float2*)(Wd2 + c);
    const float2 wr1 = *(const float2*)(Wd2 + 64 + c);
    const float2 wr2 = *(const float2*)(Wd2 + 128 + c);
    const float2 bbv = *(const float2*)(bd2p + c);
    const u64t wr0p = pk2(wr0.x, wr0.y);
    const u64t wr1p = pk2(wr1.x, wr1.y);
    const u64t wr2p = pk2(wr2.x, wr2.y);
    const u64t bbp  = pk2(bbv.x, bbv.y);
    const u64t negp = pk2(-1.f, -1.f);
    u64t sp = 0ull, qp2 = 0ull;           // packed (s0,s1), (q0,q1)
    int cur = 0;
    int p = warp;
    if (lane < 16) {
        sj[w][0][lane] = knn[p*KK + lane];
        const float* dp = g_d1 + (p*KK + lane)*3;
        const float t0 = fmaxf(ad0*dp[0] + bd0,  0.f);
        const float t1 = fmaxf(ad1*dp[1] + bd1v, 0.f);
        const float t2 = fmaxf(ad2*dp[2] + bd2v, 0.f);
        st[w][0][lane][0] = pk2(t0, t0);
        st[w][0][lane][1] = pk2(t1, t1);
        st[w][0][lane][2] = pk2(t2, t2);
    }
    __syncwarp();
    while (p < PTS) {
        const int pn = p + nw;
        if (pn < PTS && lane < 16) {
            const int nb = cur ^ 1;
            sj[w][nb][lane] = knn[pn*KK + lane];
            const float* dp = g_d1 + (pn*KK + lane)*3;
            const float t0 = fmaxf(ad0*dp[0] + bd0,  0.f);
            const float t1 = fmaxf(ad1*dp[1] + bd1v, 0.f);
            const float t2 = fmaxf(ad2*dp[2] + bd2v, 0.f);
            st[w][nb][lane][0] = pk2(t0, t0);
            st[w][nb][lane][1] = pk2(t1, t1);
            st[w][nb][lane][2] = pk2(t2, t2);
        }
        const int b = p >> 14;
        const u64t qvp = *(const u64t*)(g_q + p*CC + c);
        const u64t qbp = add2p(qvp, bbp);     // q + bb (packed)
        #pragma unroll
        for (int k = 0; k < KK; k++) {
            const int j = sj[w][cur][k];
            const u64t krp = *(const u64t*)(g_k + ((b<<14) + j)*CC + c);
            u64t x = fma2p(negp, krp, qbp);   // q + bb - kr
            x = fma2p(st[w][cur][k][0], wr0p, x);
            x = fma2p(st[w][cur][k][1], wr1p, x);
            x = fma2p(st[w][cur][k][2], wr2p, x);
            sp  = add2p(sp, x);
            qp2 = fma2p(x, x, qp2);
        }
        __syncwarp();
        cur ^= 1;
        p = pn;
    }
    float s0, s1, q0, q1;
    upk2(sp, s0, s1);
    upk2(qp2, q0, q1);
    atomicAdd(&red[c],        s0);
    atomicAdd(&red[c + 1],    s1);
    atomicAdd(&red[64 + c],   q0);
    atomicAdd(&red[64 + c+1], q1);
    __syncthreads();
    // g_acc[6..69]=sum, g_acc[70..133]=sq  -> contiguous with red[0..127]
    if (t < 128) atomicAdd(&g_acc[6 + t], (double)red[t]);
    // last block finalizes the 64-channel g1-BN into g_bn[6..133]
    if (last_block(1, t, &sLast)) {
        if (t < 64) {
            const double inv = 1.0 / (double)ITEMS;
            const double m = __ldcg(&g_acc[6 + t])  * inv;
            const double v = __ldcg(&g_acc[70 + t]) * inv - m*m;
            const float a = g1g[t] * rsqrtf((float)v + 1e-5f);
            g_bn[6 + t]  = a;
            g_bn[70 + t] = be1[t] - (float)m * a;
        }
    }
}

// ---------------- kernel 4: h1 pass (packed f32x2) + g2-BN finalize --------
// g1-BN folded; weights pre-permuted (slot i holds output aBase^i) -> the
// value-splitting butterfly is select-free and operates on packed pairs.
__global__ void __launch_bounds__(256, 4) k_h1(
                     const int* __restrict__ knn, const float* __restrict__ Wd2,
                     const float* __restrict__ bd2p, const float* __restrict__ Wg1,
                     const float* __restrict__ bg1,
                     const float* __restrict__ g2g, const float* __restrict__ be2) {
    __shared__ u64t  st[8][2][16][3];     // duplicated (t,t) pairs
    __shared__ int   sj[8][2][16];
    __shared__ float red[16];    // [0..7]=sum, [8..15]=sq
    __shared__ int   sLast;
    const int t = threadIdx.x;
    if (t < 16) red[t] = 0.f;
    __syncthreads();
    const int lane = t & 31, w = t >> 5;
    const int warp = (blockIdx.x*blockDim.x + t) >> 5;
    const int nw   = (gridDim.x*blockDim.x) >> 5;
    const int c = lane * 2;
    const float ad0=g_bn[0], ad1=g_bn[1], ad2=g_bn[2];
    const float bd0=g_bn[3], bd1v=g_bn[4], bd2v=g_bn[5];
    const float2 a1  = *(const float2*)(g_bn + 6 + c);
    const float2 b1  = *(const float2*)(g_bn + 70 + c);
    // fold a1 into pos-enc weights and bias
    const float2 wr0r = *(const float2*)(Wd2 + c);
    const float2 wr1r = *(const float2*)(Wd2 + 64 + c);
    const float2 wr2r = *(const float2*)(Wd2 + 128 + c);
    const float2 bbr  = *(const float2*)(bd2p + c);
    const u64t wr0p = pk2(a1.x*wr0r.x, a1.y*wr0r.y);
    const u64t wr1p = pk2(a1.x*wr1r.x, a1.y*wr1r.y);
    const u64t wr2p = pk2(a1.x*wr2r.x, a1.y*wr2r.y);
    const u64t bbfp = pk2(a1.x*bbr.x + b1.x, a1.y*bbr.y + b1.y);
    const u64t na1p = pk2(-a1.x, -a1.y);
    const u64t a1p  = pk2(a1.x, a1.y);
    const int aBase = (lane >> 2) & 7;           // output this lane ends up with
    // permuted weights: slot i <-> output (aBase ^ i), packed in pairs of slots
    u64t wgA01, wgA23, wgA45, wgA67, wgB01, wgB23, wgB45, wgB67;
    {
        float A[8], B[8];
        #pragma unroll
        for (int i = 0; i < 8; i++) {
            A[i] = Wg1[c*8     + (aBase ^ i)];
            B[i] = Wg1[(c+1)*8 + (aBase ^ i)];
        }
        wgA01 = pk2(A[0],A[1]); wgA23 = pk2(A[2],A[3]);
        wgA45 = pk2(A[4],A[5]); wgA67 = pk2(A[6],A[7]);
        wgB01 = pk2(B[0],B[1]); wgB23 = pk2(B[2],B[3]);
        wgB45 = pk2(B[4],B[5]); wgB67 = pk2(B[6],B[7]);
    }
    const bool isWriter = ((lane & 3) == 0);
    const float bga = bg1[aBase];
    float s2 = 0.f, q2 = 0.f;
    int cur = 0;
    int p = warp;
    if (lane < 16) {
        sj[w][0][lane] = knn[p*KK + lane];
        const float* dp = g_d1 + (p*KK + lane)*3;
        const float t0 = fmaxf(ad0*dp[0] + bd0,  0.f);
        const float t1 = fmaxf(ad1*dp[1] + bd1v, 0.f);
        const float t2 = fmaxf(ad2*dp[2] + bd2v, 0.f);
        st[w][0][lane][0] = pk2(t0, t0);
        st[w][0][lane][1] = pk2(t1, t1);
        st[w][0][lane][2] = pk2(t2, t2);
    }
    __syncwarp();
    while (p < PTS) {
        const int pn = p + nw;
        if (pn < PTS && lane < 16) {
            const int nb = cur ^ 1;
            sj[w][nb][lane] = knn[pn*KK + lane];
            const float* dp = g_d1 + (pn*KK + lane)*3;
            const float t0 = fmaxf(ad0*dp[0] + bd0,  0.f);
            const float t1 = fmaxf(ad1*dp[1] + bd1v, 0.f);
            const float t2 = fmaxf(ad2*dp[2] + bd2v, 0.f);
            st[w][nb][lane][0] = pk2(t0, t0);
            st[w][nb][lane][1] = pk2(t1, t1);
            st[w][nb][lane][2] = pk2(t2, t2);
        }
        const int b = p >> 14;
        const u64t qvp = *(const u64t*)(g_q + p*CC + c);
        const u64t qpp = fma2p(a1p, qvp, bbfp);   // a1*q + folded bias
        #pragma unroll 8
        for (int k = 0; k < KK; k++) {
            const int j = sj[w][cur][k];
            const u64t krp = *(const u64t*)(g_k + ((b<<14) + j)*CC + c);
            u64t y = fma2p(na1p, krp, qpp);
            y = fma2p(st[w][cur][k][0], wr0p, y);
            y = fma2p(st[w][cur][k][1], wr1p, y);
            y = fma2p(st[w][cur][k][2], wr2p, y);
            float y0, y1;
            upk2(y, y0, y1);
            y0 = fmaxf(y0, 0.f);
            y1 = fmaxf(y1, 0.f);
            const u64t y00 = pk2(y0, y0);
            const u64t y11 = pk2(y1, y1);
            u64t P01 = fma2p(y11, wgB01, mul2p(y00, wgA01));
            u64t P23 = fma2p(y11, wgB23, mul2p(y00, wgA23));
            u64t P45 = fma2p(y11, wgB45, mul2p(y00, wgA45));
            u64t P67 = fma2p(y11, wgB67, mul2p(y00, wgA67));
            // stage 1 (offset 16): N[i] = P[i] + partner P[i+4]
            const u64t N01 = add2p(P01, __shfl_xor_sync(0xFFFFFFFFu, P45, 16));
            const u64t N23 = add2p(P23, __shfl_xor_sync(0xFFFFFFFFu, P67, 16));
            // stage 2 (offset 8): M[i] = N[i] + partner N[i+2]
            const u64t M01 = add2p(N01, __shfl_xor_sync(0xFFFFFFFFu, N23, 8));
            // stage 3 (offset 4): v = M0 + partner M1
            float m0, m1;
            upk2(M01, m0, m1);
            float v = m0 + __shfl_xor_sync(0xFFFFFFFFu, m1, 4);
            v += __shfl_xor_sync(0xFFFFFFFFu, v, 1);
            v += __shfl_xor_sync(0xFFFFFFFFu, v, 2);
            if (isWriter) {
                const float h = v + bga;
                g_h1[(p*KK + k)*AA + aBase] = h;
                s2 += h; q2 += h*h;
            }
        }
        __syncwarp();
        cur ^= 1;
        p = pn;
    }
    if (isWriter) {
        atomicAdd(&red[aBase],     s2);
        atomicAdd(&red[8 + aBase], q2);
    }
    __syncthreads();
    // g_acc[134..141]=sum, g_acc[142..149]=sq -> contiguous with red[0..15]
    if (t < 16) atomicAdd(&g_acc[134 + t], (double)red[t]);
    // last block finalizes the 8-channel g2-BN into g_bn[134..149]
    if (last_block(2, t, &sLast)) {
        if (t < 8) {
            const double inv = 1.0 / (double)ITEMS;
            const double m = __ldcg(&g_acc[134 + t]) * inv;
            const double v = __ldcg(&g_acc[142 + t]) * inv - m*m;
            const float a = g2g[t] * rsqrtf((float)v + 1e-5f);
            g_bn[134 + t] = a;
            g_bn[142 + t] = be2[t] - (float)m * a;
        }
    }
}

// ---------------- kernel 5: h2/softmax staging + packed aggregation --------
__global__ void __launch_bounds__(256, 4) k_final(
                        const int* __restrict__ knn, const float* __restrict__ Wd2,
                        const float* __restrict__ bd2p, const float* __restrict__ Wg2,
                        const float* __restrict__ bg2, float* __restrict__ out) {
    __shared__ float sWg2[64], sa2[8], sb2[8], sbg2[8];
    __shared__ float sattn[8][2][16][8];
    __shared__ u64t  st[8][2][16][3];     // duplicated (t,t) pairs
    __shared__ int   sidx[8][2][16];
    const int t = threadIdx.x;
    if (t < 64) sWg2[t] = Wg2[t];
    if (t < 8) { sa2[t] = g_bn[134+t]; sb2[t] = g_bn[142+t]; sbg2[t] = bg2[t]; }
    __syncthreads();
    const int lane = t & 31, w = t >> 5;
    const int nw   = (gridDim.x * blockDim.x) >> 5;
    const int warp = (blockIdx.x * blockDim.x + t) >> 5;
    const int c = lane * 2;
    const float ad0=g_bn[0], ad1=g_bn[1], ad2=g_bn[2];
    const float bd0=g_bn[3], bd1v=g_bn[4], bd2v=g_bn[5];
    const float2 wr0 = *(const float2*)(Wd2 + c);
    const float2 wr1 = *(const float2*)(Wd2 + 64 + c);
    const float2 wr2 = *(const float2*)(Wd2 + 128 + c);
    const float2 bbv = *(const float2*)(bd2p + c);
    const u64t wr0p = pk2(wr0.x, wr0.y);
    const u64t wr1p = pk2(wr1.x, wr1.y);
    const u64t wr2p = pk2(wr2.x, wr2.y);
    const u64t bbp  = pk2(bbv.x, bbv.y);
    const int a = c & 7;          // even; lane covers attn indices a, a+1
    const int kk   = lane & 15;   // staging: k index
    const int half = lane >> 4;   // staging: 0 -> x 0..3, 1 -> x 4..7
    const int xb   = half * 4;

    // ---- staging lambda (all 32 lanes) ----
    auto stage = [&](int pp, int buf) {
        const int j = knn[pp*KK + kk];
        if (half == 0) sidx[w][buf][kk] = j;
        const float* hp = g_h1 + (pp*KK + kk)*AA;
        float z[8];
        #pragma unroll
        for (int x = 0; x < 8; x++) z[x] = fmaxf(sa2[x]*hp[x] + sb2[x], 0.f);
        float h2[4];
        #pragma unroll
        for (int i = 0; i < 4; i++) {
            float acc = sbg2[xb + i];
            #pragma unroll
            for (int jj = 0; jj < 8; jj++) acc += z[jj]*sWg2[jj*8 + xb + i];
            h2[i] = acc;
        }
        float mx[4];
        #pragma unroll
        for (int i = 0; i < 4; i++) mx[i] = h2[i];
        #pragma unroll
        for (int off = 8; off; off >>= 1)
            #pragma unroll
            for (int i = 0; i < 4; i++)
                mx[i] = fmaxf(mx[i], __shfl_xor_sync(0xFFFFFFFFu, mx[i], off));
        float ex[4], sm[4];
        #pragma unroll
        for (int i = 0; i < 4; i++) { ex[i] = __expf(h2[i] - mx[i]); sm[i] = ex[i]; }
        #pragma unroll
        for (int off = 8; off; off >>= 1)
            #pragma unroll
            for (int i = 0; i < 4; i++)
                sm[i] += __shfl_xor_sync(0xFFFFFFFFu, sm[i], off);
        #pragma unroll
        for (int i = 0; i < 4; i++) sattn[w][buf][kk][xb + i] = __fdividef(ex[i], sm[i]);
        if (half == 0) {
            const float* dpp = g_d1 + (pp*KK + kk)*3;
            const float t0 = fmaxf(ad0*dpp[0] + bd0,  0.f);
            const float t1 = fmaxf(ad1*dpp[1] + bd1v, 0.f);
            const float t2 = fmaxf(ad2*dpp[2] + bd2v, 0.f);
            st[w][buf][kk][0] = pk2(t0, t0);
            st[w][buf][kk][1] = pk2(t1, t1);
            st[w][buf][kk][2] = pk2(t2, t2);
        }
    };

    int cur = 0;
    int p = warp;
    stage(p, 0);
    __syncwarp();
    while (p < PTS) {
        const int pn = p + nw;
        if (pn < PTS) stage(pn, cur ^ 1);
        const int b = p >> 14;
        u64t accp = 0ull;
        #pragma unroll
        for (int k = 0; k < KK; k++) {
            const int j = sidx[w][cur][k];
            const u64t vrp = *(const u64t*)(g_v + ((b<<14) + j)*CC + c);
            u64t val = add2p(vrp, bbp);
            val = fma2p(st[w][cur][k][0], wr0p, val);
            val = fma2p(st[w][cur][k][1], wr1p, val);
            val = fma2p(st[w][cur][k][2], wr2p, val);
            const u64t atp = *(const u64t*)(&sattn[w][cur][k][a]);
            accp = fma2p(val, atp, accp);
        }
        float acc0, acc1;
        upk2(accp, acc0, acc1);
        *(float2*)(out + p*CC + c) = make_float2(acc0, acc1);
        __syncwarp();
        cur ^= 1;
        p = pn;
    }
}

// ---------------- launch ----------------------------------------------------
extern "C" void kernel_launch(void* const* d_in, const int* in_sizes, int n_in,
                              void* d_out, int out_size) {
    const float* xyz  = (const float*)d_in[0];
    const float* feat = (const float*)d_in[1];
    const int*   knn  = (const int*)  d_in[2];
    const float* Wq   = (const float*)d_in[3];  const float* bq  = (const float*)d_in[4];
    const float* Wk   = (const float*)d_in[5];  const float* bk  = (const float*)d_in[6];
    const float* Wv   = (const float*)d_in[7];  const float* bv  = (const float*)d_in[8];
    const float* Wd1  = (const float*)d_in[9];  const float* bd1 = (const float*)d_in[10];
    const float* gd   = (const float*)d_in[11]; const float* bed = (const float*)d_in[12];
    const float* Wd2  = (const float*)d_in[13]; const float* bd2 = (const float*)d_in[14];
    const float* g1   = (const float*)d_in[15]; const float* be1 = (const float*)d_in[16];
    const float* Wg1  = (const float*)d_in[17]; const float* bg1 = (const float*)d_in[18];
    const float* g2   = (const float*)d_in[19]; const float* be2 = (const float*)d_in[20];
    const float* Wg2  = (const float*)d_in[21]; const float* bg2 = (const float*)d_in[22];
    float* out = (float*)d_out;

    k_qkv   <<<512, 256>>>(feat, Wq, bq, Wk, bk, Wv, bv);
    k_d1    <<<EVEN_GRID, 256>>>(xyz, knn, Wd1, bd1, gd, bed);
    k_g1s   <<<EVEN_GRID, 256>>>(knn, Wd2, bd2, g1, be1);
    k_h1    <<<EVEN_GRID, 256>>>(knn, Wd2, bd2, Wg1, bg1, g2, be2);
    k_final <<<EVEN_GRID, 256>>>(knn, Wd2, bd2, Wg2, bg2, out);
}